// round 2
// baseline (speedup 1.0000x reference)
#include <cuda_runtime.h>

#define BLOCK   256
#define ROWS_PT 2            // 2 rows per thread = 1 f32x2 pair
#define B_TOTAL 131072
#define NFEAT   64
#define NNUM    48
#define NCAT    16
#define NCLS    32
#define H0      40
#define H1      20

typedef unsigned long long u64;

__device__ __forceinline__ u64 fma2(u64 a, u64 b, u64 c) {
    u64 d;
    asm("fma.rn.f32x2 %0, %1, %2, %3;" : "=l"(d) : "l"(a), "l"(b), "l"(c));
    return d;
}
__device__ __forceinline__ u64 pack2(float lo, float hi) {
    u64 d;
    asm("mov.b64 %0, {%1, %2};" : "=l"(d) : "f"(lo), "f"(hi));
    return d;
}
__device__ __forceinline__ void unpack2(u64 v, float& lo, float& hi) {
    asm("mov.b64 {%0, %1}, %2;" : "=f"(lo), "=f"(hi) : "l"(v));
}
__device__ __forceinline__ u64 relu2(u64 v) {     // reg-pair aliasing: just 2 FMNMX
    float lo, hi;
    unpack2(v, lo, hi);
    lo = fmaxf(lo, 0.0f);
    hi = fmaxf(hi, 0.0f);
    return pack2(lo, hi);
}

// One block = (feature f, chunk of 512 rows). Weights pre-splatted into shared
// as f32x2 pairs; W1 consumed as ulonglong2 (LDS.128 = 2 packed weights/load).
__global__ __launch_bounds__(BLOCK, 2)
void gam_num_kernel(const float* __restrict__ inputs,
                    const float* __restrict__ W0, const float* __restrict__ b0,
                    const float* __restrict__ W1, const float* __restrict__ b1,
                    const float* __restrict__ W2, const float* __restrict__ b2,
                    float* __restrict__ out)
{
    __shared__ __align__(16) u64 sW1[H0 * H1];
    __shared__ u64 sW0[H0], sB0[H0], sB1[H1], sW2[H1];
    __shared__ u64 sB2;

    const int f   = blockIdx.y;
    const int tid = threadIdx.x;

    // ---- prefetch this thread's x values (hide GMEM latency behind smem fill)
    const int row0 = (blockIdx.x * BLOCK + tid) * ROWS_PT;
    const float x0 = inputs[(row0 + 0) * NFEAT + f];
    const float x1 = inputs[(row0 + 1) * NFEAT + f];

    // ---- load + splat this feature's weights into shared ----
    for (int i = tid; i < H0; i += BLOCK) {
        float w = W0[f * H0 + i];  sW0[i] = pack2(w, w);
        float c = b0[f * H0 + i];  sB0[i] = pack2(c, c);
    }
    for (int i = tid; i < H0 * H1; i += BLOCK) {
        float w = W1[f * H0 * H1 + i];  sW1[i] = pack2(w, w);
    }
    for (int i = tid; i < H1; i += BLOCK) {
        float c = b1[f * H1 + i];  sB1[i] = pack2(c, c);
        float w = W2[f * H1 + i];  sW2[i] = pack2(w, w);
    }
    if (tid == 0) { float c = b2[f]; sB2 = pack2(c, c); }
    __syncthreads();

    const u64 xa = pack2(x0, x1);

    // h1 accumulators, init with b1
    u64 h1a[H1];
    #pragma unroll
    for (int p = 0; p < H1; p++) h1a[p] = sB1[p];

    const ulonglong2* __restrict__ sW1v = (const ulonglong2*)sW1;

    // fused layer0+layer1: h0[o] on the fly -> 20 FFMA2 per o, 10 LDS.128 per o
    #pragma unroll 2
    for (int o = 0; o < H0; o++) {
        const u64 ha = relu2(fma2(xa, sW0[o], sB0[o]));
        #pragma unroll
        for (int j = 0; j < H1 / 2; j++) {
            const ulonglong2 w = sW1v[o * (H1 / 2) + j];   // LDS.128: weights p=2j,2j+1
            h1a[2 * j + 0] = fma2(ha, w.x, h1a[2 * j + 0]);
            h1a[2 * j + 1] = fma2(ha, w.y, h1a[2 * j + 1]);
        }
    }

    // layer2: relu(h1) dot W2 + b2
    u64 oa = sB2;
    #pragma unroll
    for (int p = 0; p < H1; p++)
        oa = fma2(relu2(h1a[p]), sW2[p], oa);

    float o0, o1;
    unpack2(oa, o0, o1);
    out[(row0 + 0) * NFEAT + f] = o0;
    out[(row0 + 1) * NFEAT + f] = o1;
}

// Categorical path: out[:, 48+c] = class_bias[c, (int)inputs[:, 48+c]]
__global__ __launch_bounds__(256)
void gam_cat_kernel(const float* __restrict__ inputs,
                    const float* __restrict__ class_bias,
                    float* __restrict__ out)
{
    const int i = blockIdx.x * blockDim.x + threadIdx.x;  // over B*16
    if (i >= B_TOTAL * NCAT) return;
    const int row = i >> 4;
    const int c   = i & 15;
    const int idx = (int)inputs[row * NFEAT + NNUM + c];
    out[row * NFEAT + NNUM + c] = class_bias[c * NCLS + idx];
}

extern "C" void kernel_launch(void* const* d_in, const int* in_sizes, int n_in,
                              void* d_out, int out_size)
{
    const float* inputs     = (const float*)d_in[0];
    const float* W0         = (const float*)d_in[1];
    const float* b0         = (const float*)d_in[2];
    const float* W1         = (const float*)d_in[3];
    const float* b1         = (const float*)d_in[4];
    const float* W2         = (const float*)d_in[5];
    const float* b2         = (const float*)d_in[6];
    const float* class_bias = (const float*)d_in[7];
    float* out = (float*)d_out;

    dim3 grid(B_TOTAL / (BLOCK * ROWS_PT), NNUM);   // 256 x 48
    gam_num_kernel<<<grid, BLOCK>>>(inputs, W0, b0, W1, b1, W2, b2, out);

    const int cat_total = B_TOTAL * NCAT;
    gam_cat_kernel<<<(cat_total + 255) / 256, 256>>>(inputs, class_bias, out);
}

// round 3
// speedup vs baseline: 1.3406x; 1.3406x over previous
#include <cuda_runtime.h>

#define BLOCK   128
#define ROWS_PT 4            // 4 rows per thread = 2 f32x2 pairs
#define B_TOTAL 131072
#define NFEAT   64
#define NNUM    48
#define NCAT    16
#define NCLS    32
#define H0      40
#define H1      20

typedef unsigned long long u64;

__device__ __forceinline__ u64 fma2(u64 a, u64 b, u64 c) {
    u64 d;
    asm("fma.rn.f32x2 %0, %1, %2, %3;" : "=l"(d) : "l"(a), "l"(b), "l"(c));
    return d;
}
__device__ __forceinline__ u64 pack2(float lo, float hi) {
    u64 d;
    asm("mov.b64 %0, {%1, %2};" : "=l"(d) : "f"(lo), "f"(hi));
    return d;
}
__device__ __forceinline__ void unpack2(u64 v, float& lo, float& hi) {
    asm("mov.b64 {%0, %1}, %2;" : "=f"(lo), "=f"(hi) : "l"(v));
}
__device__ __forceinline__ u64 relu2(u64 v) {     // reg-pair aliasing: 2 FMNMX
    float lo, hi;
    unpack2(v, lo, hi);
    lo = fmaxf(lo, 0.0f);
    hi = fmaxf(hi, 0.0f);
    return pack2(lo, hi);
}

// One block = (feature f, chunk of 512 rows), 128 threads x 4 rows.
// Weights pre-splatted to f32x2 in shared; W1 read as ulonglong2 (LDS.128 =
// 2 packed weights per load, each feeding 2 FFMA2 => 1 LDS per 4 FFMA2).
__global__ __launch_bounds__(BLOCK)
void gam_num_kernel(const float* __restrict__ inputs,
                    const float* __restrict__ W0, const float* __restrict__ b0,
                    const float* __restrict__ W1, const float* __restrict__ b1,
                    const float* __restrict__ W2, const float* __restrict__ b2,
                    float* __restrict__ out)
{
    __shared__ __align__(16) u64 sW1[H0 * H1];
    __shared__ u64 sW0[H0], sB0[H0], sB1[H1], sW2[H1];
    __shared__ u64 sB2;

    const int f   = blockIdx.y;
    const int tid = threadIdx.x;

    // prefetch this thread's x values (hide GMEM latency behind smem fill)
    const int row0 = (blockIdx.x * BLOCK + tid) * ROWS_PT;
    const float x0 = inputs[(row0 + 0) * NFEAT + f];
    const float x1 = inputs[(row0 + 1) * NFEAT + f];
    const float x2 = inputs[(row0 + 2) * NFEAT + f];
    const float x3 = inputs[(row0 + 3) * NFEAT + f];

    // load + splat this feature's weights into shared
    for (int i = tid; i < H0 * H1; i += BLOCK) {
        float w = W1[f * H0 * H1 + i];  sW1[i] = pack2(w, w);
    }
    if (tid < H0) {
        float w = W0[f * H0 + tid];  sW0[tid] = pack2(w, w);
        float c = b0[f * H0 + tid];  sB0[tid] = pack2(c, c);
    }
    if (tid < H1) {
        float c = b1[f * H1 + tid];  sB1[tid] = pack2(c, c);
        float w = W2[f * H1 + tid];  sW2[tid] = pack2(w, w);
    }
    if (tid == 0) { float c = b2[f]; sB2 = pack2(c, c); }
    __syncthreads();

    const u64 xa = pack2(x0, x1);
    const u64 xb = pack2(x2, x3);

    // h1 accumulators, init with b1
    u64 h1a[H1], h1b[H1];
    #pragma unroll
    for (int p = 0; p < H1; p++) { h1a[p] = sB1[p]; h1b[p] = sB1[p]; }

    const ulonglong2* __restrict__ sW1v = (const ulonglong2*)sW1;

    // fused layer0+layer1: per o => 10 LDS.128 + 40 FFMA2
    #pragma unroll 4
    for (int o = 0; o < H0; o++) {
        const u64 w0 = sW0[o];
        const u64 c0 = sB0[o];
        const u64 ha = relu2(fma2(xa, w0, c0));
        const u64 hb = relu2(fma2(xb, w0, c0));
        #pragma unroll
        for (int j = 0; j < H1 / 2; j++) {
            const ulonglong2 w = sW1v[o * (H1 / 2) + j];  // LDS.128 broadcast
            h1a[2 * j + 0] = fma2(ha, w.x, h1a[2 * j + 0]);
            h1b[2 * j + 0] = fma2(hb, w.x, h1b[2 * j + 0]);
            h1a[2 * j + 1] = fma2(ha, w.y, h1a[2 * j + 1]);
            h1b[2 * j + 1] = fma2(hb, w.y, h1b[2 * j + 1]);
        }
    }

    // layer2: relu(h1) dot W2 + b2
    u64 oa = sB2, ob = sB2;
    #pragma unroll
    for (int p = 0; p < H1; p++) {
        const u64 w = sW2[p];
        oa = fma2(relu2(h1a[p]), w, oa);
        ob = fma2(relu2(h1b[p]), w, ob);
    }

    float o0, o1, o2, o3;
    unpack2(oa, o0, o1);
    unpack2(ob, o2, o3);
    out[(row0 + 0) * NFEAT + f] = o0;
    out[(row0 + 1) * NFEAT + f] = o1;
    out[(row0 + 2) * NFEAT + f] = o2;
    out[(row0 + 3) * NFEAT + f] = o3;
}

// Categorical path: out[:, 48+c] = class_bias[c, (int)inputs[:, 48+c]]
__global__ __launch_bounds__(256)
void gam_cat_kernel(const float* __restrict__ inputs,
                    const float* __restrict__ class_bias,
                    float* __restrict__ out)
{
    const int i = blockIdx.x * blockDim.x + threadIdx.x;  // over B*16
    if (i >= B_TOTAL * NCAT) return;
    const int row = i >> 4;
    const int c   = i & 15;
    const int idx = (int)inputs[row * NFEAT + NNUM + c];
    out[row * NFEAT + NNUM + c] = class_bias[c * NCLS + idx];
}

extern "C" void kernel_launch(void* const* d_in, const int* in_sizes, int n_in,
                              void* d_out, int out_size)
{
    const float* inputs     = (const float*)d_in[0];
    const float* W0         = (const float*)d_in[1];
    const float* b0         = (const float*)d_in[2];
    const float* W1         = (const float*)d_in[3];
    const float* b1         = (const float*)d_in[4];
    const float* W2         = (const float*)d_in[5];
    const float* b2         = (const float*)d_in[6];
    const float* class_bias = (const float*)d_in[7];
    float* out = (float*)d_out;

    // cat kernel FIRST: makes ncu's "-s 5" land on gam_num_kernel.
    const int cat_total = B_TOTAL * NCAT;
    gam_cat_kernel<<<(cat_total + 255) / 256, 256>>>(inputs, class_bias, out);

    dim3 grid(B_TOTAL / (BLOCK * ROWS_PT), NNUM);   // 256 x 48
    gam_num_kernel<<<grid, BLOCK>>>(inputs, W0, b0, W1, b1, W2, b2, out);
}

// round 4
// speedup vs baseline: 3.7110x; 2.7682x over previous
#include <cuda_runtime.h>

#define B_TOTAL 131072
#define NFEAT   64
#define NNUM    48
#define NCAT    16
#define NCLS    32
#define H0      40
#define H1      20
#define TBL     1024
#define KCLAMP  1.0e4f

// PWL tables (device-global scratch; allocation-free)
__device__ float  g_x[NNUM][TBL];
__device__ float2 g_ys[NNUM][TBL];    // (y, slope-to-next)
__device__ float  g_sl[NNUM];         // left-tail slope

// ---------------------------------------------------------------------------
// Setup: build the exact piecewise-linear table for each numeric feature.
// The per-feature net  x -> W2^T relu(W1^T relu(w0 x + b0) + b1) + b2  is
// exactly PWL in scalar x. Knots = layer0 zeros U layer1 zero-crossings.
// ---------------------------------------------------------------------------
__global__ __launch_bounds__(256)
void gam_setup_kernel(const float* __restrict__ W0, const float* __restrict__ b0,
                      const float* __restrict__ W1, const float* __restrict__ b1,
                      const float* __restrict__ W2, const float* __restrict__ b2)
{
    const int f   = blockIdx.x;
    const int tid = threadIdx.x;

    __shared__ float sa[H0], sc[H0], sk[H0];
    __shared__ float sH[H0 + 2][H1];          // h1 at 40 knots + left/right probes
    __shared__ float list[TBL];               // knot candidates, later y values
    __shared__ float sx[TBL];                 // sorted knots
    __shared__ float sW1[H0 * H1], sb1[H1], sW2[H1];
    __shared__ float syl, syr, sb2v;
    __shared__ int   cnt;

    if (tid == 0) cnt = 0;
    if (tid < H0) { sa[tid] = W0[f * H0 + tid]; sc[tid] = b0[f * H0 + tid]; }
    for (int i = tid; i < H0 * H1; i += 256) sW1[i] = W1[f * H0 * H1 + i];
    if (tid < H1) { sb1[tid] = b1[f * H1 + tid]; sW2[tid] = W2[f * H1 + tid]; }
    if (tid == 0) sb2v = b2[f];
    __syncthreads();

    // layer0 knots (clamped), stable rank-sort into sk
    if (tid < H0) {
        float a = sa[tid], c = sc[tid];
        float kx = (a != 0.0f) ? fminf(fmaxf(-c / a, -KCLAMP), KCLAMP) : KCLAMP;
        int r = 0;
        for (int j = 0; j < H0; j++) {
            float aj = sa[j], cj = sc[j];
            float kj = (aj != 0.0f) ? fminf(fmaxf(-cj / aj, -KCLAMP), KCLAMP) : KCLAMP;
            if (kj < kx || (kj == kx && j < tid)) r++;
        }
        sk[r] = kx;
    }
    __syncthreads();

    // h1[p] evaluated exactly at each sorted knot, plus probes at t0-1, t39+1
    for (int idx = tid; idx < (H0 + 2) * H1; idx += 256) {
        int k = idx / H1, p = idx % H1;
        float x = (k < H0) ? sk[k] : (k == H0 ? sk[0] - 1.0f : sk[H0 - 1] + 1.0f);
        float acc = sb1[p];
        for (int o = 0; o < H0; o++)
            acc += sW1[o * H1 + p] * fmaxf(sa[o] * x + sc[o], 0.0f);
        sH[k][p] = acc;
    }
    if (tid < H0) list[atomicAdd(&cnt, 1)] = sk[tid];   // base knots
    __syncthreads();

    // interior zero-crossings of h1[p] (h1 is linear within each knot segment)
    for (int idx = tid; idx < (H0 - 1) * H1; idx += 256) {
        int k = idx / H1, p = idx % H1;
        float y0 = sH[k][p], y1 = sH[k + 1][p];
        if ((y0 > 0.0f) != (y1 > 0.0f)) {
            float xs = sk[k] - y0 * (sk[k + 1] - sk[k]) / (y1 - y0);
            xs = fminf(fmaxf(xs, -KCLAMP), KCLAMP);
            list[atomicAdd(&cnt, 1)] = xs;
        }
    }
    // tail crossings (h1 linear beyond the extreme knots; slope by finite diff)
    if (tid < H1) {
        int p = tid;
        float y0 = sH[0][p];
        float sl = sH[0][p] - sH[H0][p];           // slope on (t0-1, t0)
        if (sl != 0.0f && y0 != 0.0f && (y0 / sl) > 0.0f) {
            float xs = fminf(fmaxf(sk[0] - y0 / sl, -KCLAMP), KCLAMP);
            list[atomicAdd(&cnt, 1)] = xs;
        }
        float y1 = sH[H0 - 1][p];
        float sr = sH[H0 + 1][p] - sH[H0 - 1][p];  // slope on (t39, t39+1)
        if (sr != 0.0f && y1 != 0.0f && (y1 / sr) < 0.0f) {
            float xs = fminf(fmaxf(sk[H0 - 1] - y1 / sr, -KCLAMP), KCLAMP);
            list[atomicAdd(&cnt, 1)] = xs;
        }
    }
    __syncthreads();
    const int n = cnt;   // 40 <= n <= 860

    // stable rank-sort list[0..n) -> sx, pad rest with +huge
    for (int i = tid; i < n; i += 256) {
        float v = list[i];
        int r = 0;
        for (int j = 0; j < n; j++) {
            float u = list[j];
            r += (u < v) || (u == v && j < i);
        }
        sx[r] = v;
    }
    for (int i = tid; i < TBL; i += 256)
        if (i >= n) sx[i] = 3.4e38f;
    __syncthreads();

    // exact full-network evals at every knot + two tail probes
    for (int idx = tid; idx < n + 2; idx += 256) {
        float x = (idx == 0)     ? sx[0] - 1.0f
                : (idx == n + 1) ? sx[n - 1] + 1.0f
                                 : sx[idx - 1];
        float h1v[H1];
        #pragma unroll
        for (int p = 0; p < H1; p++) h1v[p] = sb1[p];
        for (int o = 0; o < H0; o++) {
            float h0 = fmaxf(sa[o] * x + sc[o], 0.0f);
            #pragma unroll
            for (int p = 0; p < H1; p++) h1v[p] += sW1[o * H1 + p] * h0;
        }
        float yv = sb2v;
        #pragma unroll
        for (int p = 0; p < H1; p++) yv += sW2[p] * fmaxf(h1v[p], 0.0f);
        if (idx == 0) syl = yv;
        else if (idx == n + 1) syr = yv;
        else list[idx - 1] = yv;
    }
    __syncthreads();

    // emit table: x, (y, slope)
    for (int k = tid; k < TBL; k += 256) {
        float xk = sx[k];
        float yk = (k < n) ? list[k] : 0.0f;
        float s;
        if (k < n - 1) {
            float dx = sx[k + 1] - xk;
            s = (dx > 0.0f) ? (list[k + 1] - yk) / dx : 0.0f;
        } else if (k == n - 1) {
            s = syr - yk;                    // right-tail slope (dx = 1)
        } else {
            s = 0.0f;
        }
        g_x[f][k]  = xk;
        g_ys[f][k] = make_float2(yk, s);
    }
    if (tid == 0) g_sl[f] = list[0] - syl;   // left-tail slope (dx = 1)
}

// ---------------------------------------------------------------------------
// Main numeric kernel: table lookup + lerp per (row, feature)
// ---------------------------------------------------------------------------
#define MBLOCK 256
#define MROWS  8

__global__ __launch_bounds__(MBLOCK)
void gam_num_kernel(const float* __restrict__ inputs, float* __restrict__ out)
{
    __shared__ float  tx[TBL];
    __shared__ float2 tys[TBL];
    const int f   = blockIdx.y;
    const int tid = threadIdx.x;

    for (int i = tid; i < TBL; i += MBLOCK) {
        tx[i]  = g_x[f][i];
        tys[i] = g_ys[f][i];
    }
    const float sl = g_sl[f];
    __syncthreads();
    const float x0 = tx[0];

    const int base = blockIdx.x * (MBLOCK * MROWS) + tid;
    #pragma unroll
    for (int r = 0; r < MROWS; r++) {
        const int row = base + r * MBLOCK;
        const float xv = inputs[row * NFEAT + f];
        int k = 0;
        float xk = x0;
        #pragma unroll
        for (int b = 512; b >= 1; b >>= 1) {
            int t = k + b;
            float xt = tx[t];
            if (xt <= xv) { k = t; xk = xt; }
        }
        float2 ys = tys[k];
        float slope = (xv < x0) ? sl : ys.y;
        out[row * NFEAT + f] = fmaf(xv - xk, slope, ys.x);
    }
}

// Categorical path: out[:, 48+c] = class_bias[c, (int)inputs[:, 48+c]]
__global__ __launch_bounds__(256)
void gam_cat_kernel(const float* __restrict__ inputs,
                    const float* __restrict__ class_bias,
                    float* __restrict__ out)
{
    const int i = blockIdx.x * blockDim.x + threadIdx.x;  // over B*16
    if (i >= B_TOTAL * NCAT) return;
    const int row = i >> 4;
    const int c   = i & 15;
    const int idx = (int)inputs[row * NFEAT + NNUM + c];
    out[row * NFEAT + NNUM + c] = class_bias[c * NCLS + idx];
}

extern "C" void kernel_launch(void* const* d_in, const int* in_sizes, int n_in,
                              void* d_out, int out_size)
{
    const float* inputs     = (const float*)d_in[0];
    const float* W0         = (const float*)d_in[1];
    const float* b0         = (const float*)d_in[2];
    const float* W1         = (const float*)d_in[3];
    const float* b1         = (const float*)d_in[4];
    const float* W2         = (const float*)d_in[5];
    const float* b2         = (const float*)d_in[6];
    const float* class_bias = (const float*)d_in[7];
    float* out = (float*)d_out;

    gam_setup_kernel<<<NNUM, 256>>>(W0, b0, W1, b1, W2, b2);

    const int cat_total = B_TOTAL * NCAT;
    gam_cat_kernel<<<(cat_total + 255) / 256, 256>>>(inputs, class_bias, out);

    dim3 grid(B_TOTAL / (MBLOCK * MROWS), NNUM);   // 64 x 48
    gam_num_kernel<<<grid, MBLOCK>>>(inputs, out);
}

// round 5
// speedup vs baseline: 5.0908x; 1.3718x over previous
#include <cuda_runtime.h>

#define B_TOTAL 131072
#define NFEAT   64
#define NNUM    48
#define NCAT    16
#define NCLS    32
#define H0      40
#define H1      20
#define TBL     1024
#define NCELL   4096
#define KCLAMP  1.0e4f
#define XSYNTH  -16.0f

// device-global scratch (allocation-free)
__device__ float          g_x[NNUM][TBL];     // knot x, padded +huge
__device__ float2         g_ys[NNUM][TBL];    // (y, slope-to-next)
__device__ unsigned short g_bk[NNUM][NCELL];  // bucket -> knot index
__device__ float          g_xT[NNUM * B_TOTAL];   // column-major inputs
__device__ float          g_yT[NFEAT * B_TOTAL];  // column-major outputs

// ---------------------------------------------------------------------------
// Setup: exact PWL table per numeric feature (1024 threads/block, 48 blocks).
// Net is exactly PWL in scalar x: knots = layer0 zeros U h1 zero-crossings.
// ---------------------------------------------------------------------------
__global__ __launch_bounds__(1024)
void gam_setup_kernel(const float* __restrict__ W0, const float* __restrict__ b0,
                      const float* __restrict__ W1, const float* __restrict__ b1,
                      const float* __restrict__ W2, const float* __restrict__ b2)
{
    const int f   = blockIdx.x;
    const int tid = threadIdx.x;

    __shared__ float sa[H0], sc[H0], sk[H0];
    __shared__ float sH[H0 + 2][H1];      // h1 at 40 base knots + L/R probes
    __shared__ float list[TBL];           // candidates, later y values
    __shared__ float sx[TBL];             // sorted knots
    __shared__ float sW1[H0 * H1], sb1[H1], sW2[H1];
    __shared__ float syr, sb2v;
    __shared__ int   cnt;

    if (tid == 0) cnt = 0;
    if (tid < H0) { sa[tid] = W0[f * H0 + tid]; sc[tid] = b0[f * H0 + tid]; }
    for (int i = tid; i < H0 * H1; i += 1024) sW1[i] = W1[f * H0 * H1 + i];
    if (tid < H1) { sb1[tid] = b1[f * H1 + tid]; sW2[tid] = W2[f * H1 + tid]; }
    if (tid == 0) sb2v = b2[f];
    __syncthreads();

    // layer0 knots (clamped), stable rank-sort into sk
    if (tid < H0) {
        float a = sa[tid], c = sc[tid];
        float kx = (a != 0.0f) ? fminf(fmaxf(-c / a, -KCLAMP), KCLAMP) : KCLAMP;
        int r = 0;
        for (int j = 0; j < H0; j++) {
            float aj = sa[j], cj = sc[j];
            float kj = (aj != 0.0f) ? fminf(fmaxf(-cj / aj, -KCLAMP), KCLAMP) : KCLAMP;
            if (kj < kx || (kj == kx && j < tid)) r++;
        }
        sk[r] = kx;
    }
    __syncthreads();

    // h1[p] exactly at each sorted base knot + probes at sk0-1, sk39+1
    for (int idx = tid; idx < (H0 + 2) * H1; idx += 1024) {
        int k = idx / H1, p = idx % H1;
        float x = (k < H0) ? sk[k] : (k == H0 ? sk[0] - 1.0f : sk[H0 - 1] + 1.0f);
        float acc = sb1[p];
        for (int o = 0; o < H0; o++)
            acc += sW1[o * H1 + p] * fmaxf(sa[o] * x + sc[o], 0.0f);
        sH[k][p] = acc;
    }
    if (tid < H0) list[atomicAdd(&cnt, 1)] = sk[tid];      // base knots
    if (tid == 0) list[atomicAdd(&cnt, 1)] = XSYNTH;       // synthetic left anchor
    __syncthreads();

    // interior zero-crossings of h1[p]
    for (int idx = tid; idx < (H0 - 1) * H1; idx += 1024) {
        int k = idx / H1, p = idx % H1;
        float y0 = sH[k][p], y1 = sH[k + 1][p];
        if ((y0 > 0.0f) != (y1 > 0.0f)) {
            float xs = sk[k] - y0 * (sk[k + 1] - sk[k]) / (y1 - y0);
            xs = fminf(fmaxf(xs, -KCLAMP), KCLAMP);
            list[atomicAdd(&cnt, 1)] = xs;
        }
    }
    // tail crossings (finite-difference slopes from probes)
    if (tid < H1) {
        int p = tid;
        float y0 = sH[0][p];
        float sl = sH[0][p] - sH[H0][p];
        if (sl != 0.0f && y0 != 0.0f && (y0 / sl) > 0.0f) {
            float xs = fminf(fmaxf(sk[0] - y0 / sl, -KCLAMP), KCLAMP);
            list[atomicAdd(&cnt, 1)] = xs;
        }
        float y1 = sH[H0 - 1][p];
        float sr = sH[H0 + 1][p] - sH[H0 - 1][p];
        if (sr != 0.0f && y1 != 0.0f && (y1 / sr) < 0.0f) {
            float xs = fminf(fmaxf(sk[H0 - 1] - y1 / sr, -KCLAMP), KCLAMP);
            list[atomicAdd(&cnt, 1)] = xs;
        }
    }
    __syncthreads();
    const int n = cnt;   // <= 861

    // stable rank-sort list[0..n) -> sx, pad with +huge
    for (int i = tid; i < n; i += 1024) {
        float v = list[i];
        int r = 0;
        for (int j = 0; j < n; j++) {
            float u = list[j];
            r += (u < v) || (u == v && j < i);
        }
        sx[r] = v;
    }
    for (int i = tid; i < TBL; i += 1024)
        if (i >= n) sx[i] = 3.4e38f;
    __syncthreads();

    // exact full-network evals at every knot + right probe
    for (int idx = tid; idx < n + 1; idx += 1024) {
        float x = (idx == n) ? sx[n - 1] + 1.0f : sx[idx];
        float h1v[H1];
        #pragma unroll
        for (int p = 0; p < H1; p++) h1v[p] = sb1[p];
        for (int o = 0; o < H0; o++) {
            float h0 = fmaxf(sa[o] * x + sc[o], 0.0f);
            #pragma unroll
            for (int p = 0; p < H1; p++) h1v[p] += sW1[o * H1 + p] * h0;
        }
        float yv = sb2v;
        #pragma unroll
        for (int p = 0; p < H1; p++) yv += sW2[p] * fmaxf(h1v[p], 0.0f);
        if (idx == n) syr = yv; else list[idx] = yv;
    }
    __syncthreads();

    // emit table (x, y, slope)
    for (int k = tid; k < TBL; k += 1024) {
        float xk = sx[k];
        float yk = (k < n) ? list[k] : 0.0f;
        float s = 0.0f;
        if (k < n - 1) {
            float dx = sx[k + 1] - xk;
            if (dx > 0.0f) s = (list[k + 1] - yk) / dx;
        } else if (k == n - 1) {
            s = syr - yk;                  // right tail (dx = 1)
        }
        g_x[f][k]  = xk;
        g_ys[f][k] = make_float2(yk, s);
    }
    // bucket LUT: cell c over [-8,8] -> last knot with x <= cell_left
    for (int c = tid; c < NCELL; c += 1024) {
        float cl = -8.0f + (float)c * (16.0f / NCELL);
        int k = 0;
        #pragma unroll
        for (int b = 512; b >= 1; b >>= 1) {
            int t = k + b;
            if (t < TBL && sx[t] <= cl) k = t;
        }
        g_bk[f][c] = (unsigned short)k;
    }
}

// ---------------------------------------------------------------------------
// K1: coalesced load -> smem transpose -> g_xT (num) + cat lookups -> g_yT
// ---------------------------------------------------------------------------
#define T1R 128
__global__ __launch_bounds__(256)
void gam_pre_kernel(const float* __restrict__ inputs,
                    const float* __restrict__ class_bias)
{
    __shared__ float s[T1R][NFEAT + 1];
    __shared__ float scb[NCAT * NCLS];
    const int tid  = threadIdx.x;
    const int row0 = blockIdx.x * T1R;

    for (int i = tid; i < NCAT * NCLS; i += 256) scb[i] = class_bias[i];

    const float4* inp4 = (const float4*)(inputs + (size_t)row0 * NFEAT);
    for (int v = tid; v < T1R * (NFEAT / 4); v += 256) {
        int r = v >> 4, c4 = v & 15;
        float4 d = inp4[v];
        s[r][c4 * 4 + 0] = d.x; s[r][c4 * 4 + 1] = d.y;
        s[r][c4 * 4 + 2] = d.z; s[r][c4 * 4 + 3] = d.w;
    }
    __syncthreads();

    for (int it = tid; it < NNUM * T1R; it += 256) {
        int f = it / T1R, r = it % T1R;
        g_xT[f * B_TOTAL + row0 + r] = s[r][f];
    }
    for (int it = tid; it < NCAT * T1R; it += 256) {
        int c = it / T1R, r = it % T1R;
        int idx = (int)s[r][NNUM + c];
        g_yT[(NNUM + c) * B_TOTAL + row0 + r] = scb[c * NCLS + idx];
    }
}

// ---------------------------------------------------------------------------
// K2: contiguous column read, bucket + scan + lerp, contiguous column write
// ---------------------------------------------------------------------------
__device__ __forceinline__ float lut_eval(float xv, const float* tx,
                                          const float2* tys,
                                          const unsigned short* sb)
{
    int cell = __float2int_rz(fmaf(xv, (float)NCELL / 16.0f, (float)NCELL / 2));
    cell = max(0, min(NCELL - 1, cell));
    int k = sb[cell];
    while (tx[k + 1] <= xv) k++;
    float2 ys = tys[k];
    return fmaf(xv - tx[k], ys.y, ys.x);
}

__global__ __launch_bounds__(256)
void gam_lut_kernel()
{
    __shared__ float          tx[TBL];
    __shared__ float2         tys[TBL];
    __shared__ unsigned short sb[NCELL];
    const int f   = blockIdx.y;
    const int tid = threadIdx.x;

    for (int i = tid; i < TBL; i += 256) { tx[i] = g_x[f][i]; tys[i] = g_ys[f][i]; }
    const unsigned int* gb = (const unsigned int*)g_bk[f];
    unsigned int* sbu = (unsigned int*)sb;
    for (int i = tid; i < NCELL / 2; i += 256) sbu[i] = gb[i];
    __syncthreads();

    const float4* xc = (const float4*)(g_xT + f * B_TOTAL) + blockIdx.x * 512;
    float4*       yc = (float4*)(g_yT + f * B_TOTAL) + blockIdx.x * 512;
    #pragma unroll
    for (int g = 0; g < 2; g++) {
        float4 x4 = xc[g * 256 + tid];
        float4 y4;
        y4.x = lut_eval(x4.x, tx, tys, sb);
        y4.y = lut_eval(x4.y, tx, tys, sb);
        y4.z = lut_eval(x4.z, tx, tys, sb);
        y4.w = lut_eval(x4.w, tx, tys, sb);
        yc[g * 256 + tid] = y4;
    }
}

// ---------------------------------------------------------------------------
// K3: g_yT columns -> smem transpose -> coalesced row-major out
// ---------------------------------------------------------------------------
__global__ __launch_bounds__(256)
void gam_post_kernel(float* __restrict__ out)
{
    __shared__ float s[T1R][NFEAT + 1];
    const int tid  = threadIdx.x;
    const int row0 = blockIdx.x * T1R;

    for (int it = tid; it < NFEAT * T1R; it += 256) {
        int f = it / T1R, r = it % T1R;
        s[r][f] = g_yT[f * B_TOTAL + row0 + r];
    }
    __syncthreads();

    float4* out4 = (float4*)(out + (size_t)row0 * NFEAT);
    for (int v = tid; v < T1R * (NFEAT / 4); v += 256) {
        int r = v >> 4, c4 = v & 15;
        out4[v] = make_float4(s[r][c4 * 4 + 0], s[r][c4 * 4 + 1],
                              s[r][c4 * 4 + 2], s[r][c4 * 4 + 3]);
    }
}

extern "C" void kernel_launch(void* const* d_in, const int* in_sizes, int n_in,
                              void* d_out, int out_size)
{
    const float* inputs     = (const float*)d_in[0];
    const float* W0         = (const float*)d_in[1];
    const float* b0         = (const float*)d_in[2];
    const float* W1         = (const float*)d_in[3];
    const float* b1         = (const float*)d_in[4];
    const float* W2         = (const float*)d_in[5];
    const float* b2         = (const float*)d_in[6];
    const float* class_bias = (const float*)d_in[7];
    float* out = (float*)d_out;

    gam_setup_kernel<<<NNUM, 1024>>>(W0, b0, W1, b1, W2, b2);
    gam_pre_kernel<<<B_TOTAL / T1R, 256>>>(inputs, class_bias);
    dim3 g2(B_TOTAL / 2048, NNUM);        // 64 x 48
    gam_lut_kernel<<<g2, 256>>>();
    gam_post_kernel<<<B_TOTAL / T1R, 256>>>(out);
}

// round 6
// speedup vs baseline: 6.1823x; 1.2144x over previous
#include <cuda_runtime.h>

#define B_TOTAL 131072
#define NFEAT   64
#define NNUM    48
#define NCAT    16
#define NCLS    32
#define H0      40
#define H1      20
#define TBL     1024
#define NCELL   4096
#define KCLAMP  1.0e4f
#define XSYNTH  -16.0f

// device-global scratch (allocation-free)
__device__ float          g_x[NNUM][TBL];     // knot x, padded +huge
__device__ float2         g_ys[NNUM][TBL];    // (y, slope-to-next)
__device__ unsigned short g_bk[NNUM][NCELL];  // bucket -> knot index
__device__ float          g_xT[NNUM * B_TOTAL];   // column-major numeric inputs
__device__ float          g_yT[NNUM * B_TOTAL];   // column-major numeric outputs

// ---------------------------------------------------------------------------
// Setup: exact PWL table per numeric feature.
// Net is exactly PWL in scalar x: knots = layer0 zeros U h1 zero-crossings.
// ---------------------------------------------------------------------------
__global__ __launch_bounds__(1024)
void gam_setup_kernel(const float* __restrict__ W0, const float* __restrict__ b0,
                      const float* __restrict__ W1, const float* __restrict__ b1,
                      const float* __restrict__ W2, const float* __restrict__ b2)
{
    const int f   = blockIdx.x;
    const int tid = threadIdx.x;

    __shared__ float sa[H0], sc[H0], sk[H0];
    __shared__ float sH[H0 + 2][H1];
    __shared__ float list[TBL];
    __shared__ float sx[TBL];
    __shared__ float sW1[H0 * H1], sb1[H1], sW2[H1];
    __shared__ float syr, sb2v;
    __shared__ int   cnt;

    if (tid == 0) cnt = 0;
    if (tid < H0) { sa[tid] = W0[f * H0 + tid]; sc[tid] = b0[f * H0 + tid]; }
    for (int i = tid; i < H0 * H1; i += 1024) sW1[i] = W1[f * H0 * H1 + i];
    if (tid < H1) { sb1[tid] = b1[f * H1 + tid]; sW2[tid] = W2[f * H1 + tid]; }
    if (tid == 0) sb2v = b2[f];
    __syncthreads();

    // layer0 knots (clamped), stable rank-sort into sk
    if (tid < H0) {
        float a = sa[tid], c = sc[tid];
        float kx = (a != 0.0f) ? fminf(fmaxf(-c / a, -KCLAMP), KCLAMP) : KCLAMP;
        int r = 0;
        for (int j = 0; j < H0; j++) {
            float aj = sa[j], cj = sc[j];
            float kj = (aj != 0.0f) ? fminf(fmaxf(-cj / aj, -KCLAMP), KCLAMP) : KCLAMP;
            if (kj < kx || (kj == kx && j < tid)) r++;
        }
        sk[r] = kx;
    }
    __syncthreads();

    // h1[p] exactly at each sorted base knot + probes at sk0-1, sk39+1
    for (int idx = tid; idx < (H0 + 2) * H1; idx += 1024) {
        int k = idx / H1, p = idx % H1;
        float x = (k < H0) ? sk[k] : (k == H0 ? sk[0] - 1.0f : sk[H0 - 1] + 1.0f);
        float acc = sb1[p];
        for (int o = 0; o < H0; o++)
            acc += sW1[o * H1 + p] * fmaxf(sa[o] * x + sc[o], 0.0f);
        sH[k][p] = acc;
    }
    if (tid < H0) list[atomicAdd(&cnt, 1)] = sk[tid];
    if (tid == 0) list[atomicAdd(&cnt, 1)] = XSYNTH;   // synthetic left anchor
    __syncthreads();

    // interior zero-crossings of h1[p]
    for (int idx = tid; idx < (H0 - 1) * H1; idx += 1024) {
        int k = idx / H1, p = idx % H1;
        float y0 = sH[k][p], y1 = sH[k + 1][p];
        if ((y0 > 0.0f) != (y1 > 0.0f)) {
            float xs = sk[k] - y0 * (sk[k + 1] - sk[k]) / (y1 - y0);
            xs = fminf(fmaxf(xs, -KCLAMP), KCLAMP);
            list[atomicAdd(&cnt, 1)] = xs;
        }
    }
    // tail crossings (finite-difference slopes from probes)
    if (tid < H1) {
        int p = tid;
        float y0 = sH[0][p];
        float sl = sH[0][p] - sH[H0][p];
        if (sl != 0.0f && y0 != 0.0f && (y0 / sl) > 0.0f) {
            float xs = fminf(fmaxf(sk[0] - y0 / sl, -KCLAMP), KCLAMP);
            list[atomicAdd(&cnt, 1)] = xs;
        }
        float y1 = sH[H0 - 1][p];
        float sr = sH[H0 + 1][p] - sH[H0 - 1][p];
        if (sr != 0.0f && y1 != 0.0f && (y1 / sr) < 0.0f) {
            float xs = fminf(fmaxf(sk[H0 - 1] - y1 / sr, -KCLAMP), KCLAMP);
            list[atomicAdd(&cnt, 1)] = xs;
        }
    }
    __syncthreads();
    const int n = cnt;   // <= 862

    // stable rank-sort list[0..n) -> sx, pad with +huge
    for (int i = tid; i < n; i += 1024) {
        float v = list[i];
        int r = 0;
        for (int j = 0; j < n; j++) {
            float u = list[j];
            r += (u < v) || (u == v && j < i);
        }
        sx[r] = v;
    }
    for (int i = tid; i < TBL; i += 1024)
        if (i >= n) sx[i] = 3.4e38f;
    __syncthreads();

    // exact full-network evals at every knot + right probe
    for (int idx = tid; idx < n + 1; idx += 1024) {
        float x = (idx == n) ? sx[n - 1] + 1.0f : sx[idx];
        float h1v[H1];
        #pragma unroll
        for (int p = 0; p < H1; p++) h1v[p] = sb1[p];
        for (int o = 0; o < H0; o++) {
            float h0 = fmaxf(sa[o] * x + sc[o], 0.0f);
            #pragma unroll
            for (int p = 0; p < H1; p++) h1v[p] += sW1[o * H1 + p] * h0;
        }
        float yv = sb2v;
        #pragma unroll
        for (int p = 0; p < H1; p++) yv += sW2[p] * fmaxf(h1v[p], 0.0f);
        if (idx == n) syr = yv; else list[idx] = yv;
    }
    __syncthreads();

    // emit table (x, y, slope)
    for (int k = tid; k < TBL; k += 1024) {
        float xk = sx[k];
        float yk = (k < n) ? list[k] : 0.0f;
        float s = 0.0f;
        if (k < n - 1) {
            float dx = sx[k + 1] - xk;
            if (dx > 0.0f) s = (list[k + 1] - yk) / dx;
        } else if (k == n - 1) {
            s = syr - yk;                  // right tail (dx = 1)
        }
        g_x[f][k]  = xk;
        g_ys[f][k] = make_float2(yk, s);
    }
    // bucket LUT: cell c over [-8,8] -> last knot with x <= cell_left
    for (int c = tid; c < NCELL; c += 1024) {
        float cl = -8.0f + (float)c * (16.0f / NCELL);
        int k = 0;
        #pragma unroll
        for (int b = 512; b >= 1; b >>= 1) {
            int t = k + b;
            if (t < TBL && sx[t] <= cl) k = t;
        }
        g_bk[f][c] = (unsigned short)k;
    }
}

// ---------------------------------------------------------------------------
// K1 pre: numeric columns only -> smem transpose -> g_xT (float4 both sides)
// ---------------------------------------------------------------------------
#define PRER 128

__global__ __launch_bounds__(256)
void gam_pre_kernel(const float* __restrict__ inputs)
{
    __shared__ float s[PRER][NNUM + 1];       // stride 49 words: conflict-free cols
    const int tid  = threadIdx.x;
    const int row0 = blockIdx.x * PRER;

    const float4* inp4 = (const float4*)(inputs + (size_t)row0 * NFEAT);
    #pragma unroll
    for (int i = 0; i < 6; i++) {             // 128 rows x 12 f4 (numeric only)
        int v  = i * 256 + tid;
        int r  = v / 12, c4 = v - r * 12;
        float4 d = inp4[r * 16 + c4];
        s[r][c4 * 4 + 0] = d.x; s[r][c4 * 4 + 1] = d.y;
        s[r][c4 * 4 + 2] = d.z; s[r][c4 * 4 + 3] = d.w;
    }
    __syncthreads();

    #pragma unroll
    for (int i = 0; i < 6; i++) {             // 48 feats x 32 row-quads
        int v  = i * 256 + tid;
        int f  = v >> 5, rq = v & 31;
        float4 d = make_float4(s[4 * rq + 0][f], s[4 * rq + 1][f],
                               s[4 * rq + 2][f], s[4 * rq + 3][f]);
        ((float4*)(g_xT + (size_t)f * B_TOTAL + row0))[rq] = d;
    }
}

// ---------------------------------------------------------------------------
// K2 lut: contiguous column read, bucket + scan + lerp, contiguous write
// ---------------------------------------------------------------------------
__device__ __forceinline__ float lut_eval(float xv, const float* tx,
                                          const float2* tys,
                                          const unsigned short* sb)
{
    int cell = __float2int_rz(fmaf(xv, (float)NCELL / 16.0f, (float)NCELL / 2));
    cell = max(0, min(NCELL - 1, cell));
    int k = sb[cell];
    while (tx[k + 1] <= xv) k++;
    while (k > 0 && tx[k] > xv) k--;          // guard: x below bucket grid
    float2 ys = tys[k];
    return fmaf(xv - tx[k], ys.y, ys.x);
}

#define LROWS 8192
__global__ __launch_bounds__(256)
void gam_lut_kernel()
{
    __shared__ float          tx[TBL];
    __shared__ float2         tys[TBL];
    __shared__ unsigned short sb[NCELL];
    const int f   = blockIdx.y;
    const int tid = threadIdx.x;

    // wide table loads: 4KB + 8KB + 8KB
    ((float4*)tx)[tid]        = ((const float4*)g_x[f])[tid];
    ((float4*)tys)[tid]       = ((const float4*)g_ys[f])[tid];
    ((float4*)tys)[256 + tid] = ((const float4*)g_ys[f])[256 + tid];
    ((uint4*)sb)[tid]         = ((const uint4*)g_bk[f])[tid];
    ((uint4*)sb)[256 + tid]   = ((const uint4*)g_bk[f])[256 + tid];
    __syncthreads();

    const float4* xc = (const float4*)(g_xT + (size_t)f * B_TOTAL) + blockIdx.x * (LROWS / 4);
    float4*       yc = (float4*)(g_yT + (size_t)f * B_TOTAL) + blockIdx.x * (LROWS / 4);
    #pragma unroll
    for (int g = 0; g < LROWS / 1024; g++) {
        float4 x4 = xc[g * 256 + tid];
        float4 y4;
        y4.x = lut_eval(x4.x, tx, tys, sb);
        y4.y = lut_eval(x4.y, tx, tys, sb);
        y4.z = lut_eval(x4.z, tx, tys, sb);
        y4.w = lut_eval(x4.w, tx, tys, sb);
        yc[g * 256 + tid] = y4;
    }
}

// ---------------------------------------------------------------------------
// K3 post: g_yT numeric columns + inputs cat columns -> row-major out
// ---------------------------------------------------------------------------
__global__ __launch_bounds__(256)
void gam_post_kernel(const float* __restrict__ inputs,
                     const float* __restrict__ class_bias,
                     float* __restrict__ out)
{
    __shared__ float s[PRER][NFEAT + 1];      // 128 x 65
    __shared__ float scb[NCAT * NCLS];
    const int tid  = threadIdx.x;
    const int row0 = blockIdx.x * PRER;

    if (tid < 128) ((float4*)scb)[tid] = ((const float4*)class_bias)[tid];

    #pragma unroll
    for (int i = 0; i < 6; i++) {             // numeric: 48 feats x 32 quads
        int v  = i * 256 + tid;
        int f  = v >> 5, rq = v & 31;
        float4 d = ((const float4*)(g_yT + (size_t)f * B_TOTAL + row0))[rq];
        s[4 * rq + 0][f] = d.x; s[4 * rq + 1][f] = d.y;
        s[4 * rq + 2][f] = d.z; s[4 * rq + 3][f] = d.w;
    }
    __syncthreads();                          // scb + numeric ready

    const float4* inp4 = (const float4*)(inputs + (size_t)row0 * NFEAT);
    #pragma unroll
    for (int i = 0; i < 2; i++) {             // cat: 128 rows x 4 f4
        int v  = i * 256 + tid;
        int r  = v >> 2, cc = v & 3;
        float4 d = inp4[r * 16 + 12 + cc];
        s[r][48 + cc * 4 + 0] = scb[(cc * 4 + 0) * NCLS + (int)d.x];
        s[r][48 + cc * 4 + 1] = scb[(cc * 4 + 1) * NCLS + (int)d.y];
        s[r][48 + cc * 4 + 2] = scb[(cc * 4 + 2) * NCLS + (int)d.z];
        s[r][48 + cc * 4 + 3] = scb[(cc * 4 + 3) * NCLS + (int)d.w];
    }
    __syncthreads();

    float4* out4 = (float4*)(out + (size_t)row0 * NFEAT);
    #pragma unroll
    for (int i = 0; i < 8; i++) {             // 128 rows x 16 f4
        int v  = i * 256 + tid;
        int r  = v >> 4, c4 = v & 15;
        out4[v] = make_float4(s[r][4 * c4 + 0], s[r][4 * c4 + 1],
                              s[r][4 * c4 + 2], s[r][4 * c4 + 3]);
    }
}

extern "C" void kernel_launch(void* const* d_in, const int* in_sizes, int n_in,
                              void* d_out, int out_size)
{
    const float* inputs     = (const float*)d_in[0];
    const float* W0         = (const float*)d_in[1];
    const float* b0         = (const float*)d_in[2];
    const float* W1         = (const float*)d_in[3];
    const float* b1         = (const float*)d_in[4];
    const float* W2         = (const float*)d_in[5];
    const float* b2         = (const float*)d_in[6];
    const float* class_bias = (const float*)d_in[7];
    float* out = (float*)d_out;

    gam_setup_kernel<<<NNUM, 1024>>>(W0, b0, W1, b1, W2, b2);
    gam_pre_kernel<<<B_TOTAL / PRER, 256>>>(inputs);
    dim3 g2(B_TOTAL / LROWS, NNUM);           // 16 x 48
    gam_lut_kernel<<<g2, 256>>>();
    gam_post_kernel<<<B_TOTAL / PRER, 256>>>(inputs, class_bias, out);
}

// round 7
// speedup vs baseline: 6.8713x; 1.1115x over previous
#include <cuda_runtime.h>

#define B_TOTAL 131072
#define NFEAT   64
#define NNUM    48
#define NCAT    16
#define NCLS    32
#define H0      40
#define H1      20
#define TBL     1024
#define NCELL   4096
#define KCLAMP  1.0e4f
#define XSYNTH  -16.0f

// device-global scratch (allocation-free)
__device__ float          g_x[NNUM][TBL];     // knot x, padded +huge
__device__ float2         g_ys[NNUM][TBL];    // (y, slope-to-next)
__device__ unsigned short g_bk[NNUM][NCELL];  // bucket -> knot index
__device__ float          g_xT[NNUM * B_TOTAL];  // col-major x, overwritten with y in-place

// ---------------------------------------------------------------------------
// Setup: exact PWL table per numeric feature.
// Net is exactly PWL in scalar x: knots = layer0 zeros U h1 zero-crossings.
// ---------------------------------------------------------------------------
__global__ __launch_bounds__(1024)
void gam_setup_kernel(const float* __restrict__ W0, const float* __restrict__ b0,
                      const float* __restrict__ W1, const float* __restrict__ b1,
                      const float* __restrict__ W2, const float* __restrict__ b2)
{
    const int f   = blockIdx.x;
    const int tid = threadIdx.x;

    __shared__ float sa[H0], sc[H0], sk[H0];
    __shared__ float sH[H0 + 2][H1];
    __shared__ float list[TBL];
    __shared__ float sx[TBL];
    __shared__ float sW1[H0 * H1], sb1[H1], sW2[H1];
    __shared__ float syr, sb2v;
    __shared__ int   cnt;

    if (tid == 0) cnt = 0;
    if (tid < H0) { sa[tid] = W0[f * H0 + tid]; sc[tid] = b0[f * H0 + tid]; }
    for (int i = tid; i < H0 * H1; i += 1024) sW1[i] = W1[f * H0 * H1 + i];
    if (tid < H1) { sb1[tid] = b1[f * H1 + tid]; sW2[tid] = W2[f * H1 + tid]; }
    if (tid == 0) sb2v = b2[f];
    __syncthreads();

    // layer0 knots (clamped), stable rank-sort into sk
    if (tid < H0) {
        float a = sa[tid], c = sc[tid];
        float kx = (a != 0.0f) ? fminf(fmaxf(-c / a, -KCLAMP), KCLAMP) : KCLAMP;
        int r = 0;
        for (int j = 0; j < H0; j++) {
            float aj = sa[j], cj = sc[j];
            float kj = (aj != 0.0f) ? fminf(fmaxf(-cj / aj, -KCLAMP), KCLAMP) : KCLAMP;
            if (kj < kx || (kj == kx && j < tid)) r++;
        }
        sk[r] = kx;
    }
    __syncthreads();

    // h1[p] exactly at each sorted base knot + probes at sk0-1, sk39+1
    for (int idx = tid; idx < (H0 + 2) * H1; idx += 1024) {
        int k = idx / H1, p = idx % H1;
        float x = (k < H0) ? sk[k] : (k == H0 ? sk[0] - 1.0f : sk[H0 - 1] + 1.0f);
        float acc = sb1[p];
        for (int o = 0; o < H0; o++)
            acc += sW1[o * H1 + p] * fmaxf(sa[o] * x + sc[o], 0.0f);
        sH[k][p] = acc;
    }
    if (tid < H0) list[atomicAdd(&cnt, 1)] = sk[tid];
    if (tid == 0) list[atomicAdd(&cnt, 1)] = XSYNTH;   // synthetic left anchor
    __syncthreads();

    // interior zero-crossings of h1[p]
    for (int idx = tid; idx < (H0 - 1) * H1; idx += 1024) {
        int k = idx / H1, p = idx % H1;
        float y0 = sH[k][p], y1 = sH[k + 1][p];
        if ((y0 > 0.0f) != (y1 > 0.0f)) {
            float xs = sk[k] - y0 * (sk[k + 1] - sk[k]) / (y1 - y0);
            xs = fminf(fmaxf(xs, -KCLAMP), KCLAMP);
            list[atomicAdd(&cnt, 1)] = xs;
        }
    }
    // tail crossings (finite-difference slopes from probes)
    if (tid < H1) {
        int p = tid;
        float y0 = sH[0][p];
        float sl = sH[0][p] - sH[H0][p];
        if (sl != 0.0f && y0 != 0.0f && (y0 / sl) > 0.0f) {
            float xs = fminf(fmaxf(sk[0] - y0 / sl, -KCLAMP), KCLAMP);
            list[atomicAdd(&cnt, 1)] = xs;
        }
        float y1 = sH[H0 - 1][p];
        float sr = sH[H0 + 1][p] - sH[H0 - 1][p];
        if (sr != 0.0f && y1 != 0.0f && (y1 / sr) < 0.0f) {
            float xs = fminf(fmaxf(sk[H0 - 1] - y1 / sr, -KCLAMP), KCLAMP);
            list[atomicAdd(&cnt, 1)] = xs;
        }
    }
    __syncthreads();
    const int n = cnt;   // <= 862

    // stable rank-sort list[0..n) -> sx, pad with +huge
    for (int i = tid; i < n; i += 1024) {
        float v = list[i];
        int r = 0;
        for (int j = 0; j < n; j++) {
            float u = list[j];
            r += (u < v) || (u == v && j < i);
        }
        sx[r] = v;
    }
    for (int i = tid; i < TBL; i += 1024)
        if (i >= n) sx[i] = 3.4e38f;
    __syncthreads();

    // exact full-network evals at every knot + right probe
    for (int idx = tid; idx < n + 1; idx += 1024) {
        float x = (idx == n) ? sx[n - 1] + 1.0f : sx[idx];
        float h1v[H1];
        #pragma unroll
        for (int p = 0; p < H1; p++) h1v[p] = sb1[p];
        for (int o = 0; o < H0; o++) {
            float h0 = fmaxf(sa[o] * x + sc[o], 0.0f);
            #pragma unroll
            for (int p = 0; p < H1; p++) h1v[p] += sW1[o * H1 + p] * h0;
        }
        float yv = sb2v;
        #pragma unroll
        for (int p = 0; p < H1; p++) yv += sW2[p] * fmaxf(h1v[p], 0.0f);
        if (idx == n) syr = yv; else list[idx] = yv;
    }
    __syncthreads();

    // emit table (x, y, slope)
    for (int k = tid; k < TBL; k += 1024) {
        float xk = sx[k];
        float yk = (k < n) ? list[k] : 0.0f;
        float s = 0.0f;
        if (k < n - 1) {
            float dx = sx[k + 1] - xk;
            if (dx > 0.0f) s = (list[k + 1] - yk) / dx;
        } else if (k == n - 1) {
            s = syr - yk;                  // right tail (dx = 1)
        }
        g_x[f][k]  = xk;
        g_ys[f][k] = make_float2(yk, s);
    }
    // bucket LUT: cell c over [-8,8] -> last knot with x <= cell_left
    for (int c = tid; c < NCELL; c += 1024) {
        float cl = -8.0f + (float)c * (16.0f / NCELL);
        int k = 0;
        #pragma unroll
        for (int b = 512; b >= 1; b >>= 1) {
            int t = k + b;
            if (t < TBL && sx[t] <= cl) k = t;
        }
        g_bk[f][c] = (unsigned short)k;
    }
}

// ---------------------------------------------------------------------------
// K1 pre: 64 rows/block, numeric columns -> smem transpose -> g_xT
// ---------------------------------------------------------------------------
#define PRER 64

__global__ __launch_bounds__(256)
void gam_pre_kernel(const float* __restrict__ inputs)
{
    __shared__ float s[PRER][NNUM + 1];       // 64 x 49
    const int tid  = threadIdx.x;
    const int row0 = blockIdx.x * PRER;

    const float4* inp4 = (const float4*)(inputs + (size_t)row0 * NFEAT);
    #pragma unroll
    for (int i = 0; i < 3; i++) {             // 64 rows x 12 numeric f4
        int v  = i * 256 + tid;
        int r  = v / 12, c4 = v - r * 12;
        float4 d = inp4[r * 16 + c4];
        s[r][c4 * 4 + 0] = d.x; s[r][c4 * 4 + 1] = d.y;
        s[r][c4 * 4 + 2] = d.z; s[r][c4 * 4 + 3] = d.w;
    }
    __syncthreads();

    #pragma unroll
    for (int i = 0; i < 3; i++) {             // 48 feats x 16 row-quads
        int v  = i * 256 + tid;
        int f  = v >> 4, rq = v & 15;
        float4 d = make_float4(s[4 * rq + 0][f], s[4 * rq + 1][f],
                               s[4 * rq + 2][f], s[4 * rq + 3][f]);
        ((float4*)(g_xT + (size_t)f * B_TOTAL + row0))[rq] = d;
    }
}

// ---------------------------------------------------------------------------
// K2 lut: in-place on g_xT (reads x, writes y to the same slots)
// ---------------------------------------------------------------------------
__device__ __forceinline__ float lut_eval(float xv, const float* tx,
                                          const float2* tys,
                                          const unsigned short* sb)
{
    int cell = __float2int_rz(fmaf(xv, (float)NCELL / 16.0f, (float)NCELL / 2));
    cell = max(0, min(NCELL - 1, cell));
    int k = sb[cell];
    while (tx[k + 1] <= xv) k++;
    while (k > 0 && tx[k] > xv) k--;          // guard: x below bucket grid
    float2 ys = tys[k];
    return fmaf(xv - tx[k], ys.y, ys.x);
}

#define LROWS 4096
__global__ __launch_bounds__(256)
void gam_lut_kernel()
{
    __shared__ float          tx[TBL];
    __shared__ float2         tys[TBL];
    __shared__ unsigned short sb[NCELL];
    const int f   = blockIdx.y;
    const int tid = threadIdx.x;

    ((float4*)tx)[tid]        = ((const float4*)g_x[f])[tid];
    ((float4*)tys)[tid]       = ((const float4*)g_ys[f])[tid];
    ((float4*)tys)[256 + tid] = ((const float4*)g_ys[f])[256 + tid];
    ((uint4*)sb)[tid]         = ((const uint4*)g_bk[f])[tid];
    ((uint4*)sb)[256 + tid]   = ((const uint4*)g_bk[f])[256 + tid];
    __syncthreads();

    float4* xc = (float4*)(g_xT + (size_t)f * B_TOTAL) + blockIdx.x * (LROWS / 4);
    #pragma unroll
    for (int g = 0; g < LROWS / 1024; g++) {
        float4 x4 = xc[g * 256 + tid];
        float4 y4;
        y4.x = lut_eval(x4.x, tx, tys, sb);
        y4.y = lut_eval(x4.y, tx, tys, sb);
        y4.z = lut_eval(x4.z, tx, tys, sb);
        y4.w = lut_eval(x4.w, tx, tys, sb);
        xc[g * 256 + tid] = y4;               // in-place overwrite
    }
}

// ---------------------------------------------------------------------------
// K3 post: g_xT (now y) numeric columns + inputs cat columns -> row-major out
// ---------------------------------------------------------------------------
__global__ __launch_bounds__(256)
void gam_post_kernel(const float* __restrict__ inputs,
                     const float* __restrict__ class_bias,
                     float* __restrict__ out)
{
    __shared__ float s[PRER][NFEAT + 1];      // 64 x 65
    __shared__ float scb[NCAT * NCLS];
    const int tid  = threadIdx.x;
    const int row0 = blockIdx.x * PRER;

    if (tid < 128) ((float4*)scb)[tid] = ((const float4*)class_bias)[tid];

    #pragma unroll
    for (int i = 0; i < 3; i++) {             // numeric: 48 feats x 16 quads
        int v  = i * 256 + tid;
        int f  = v >> 4, rq = v & 15;
        float4 d = ((const float4*)(g_xT + (size_t)f * B_TOTAL + row0))[rq];
        s[4 * rq + 0][f] = d.x; s[4 * rq + 1][f] = d.y;
        s[4 * rq + 2][f] = d.z; s[4 * rq + 3][f] = d.w;
    }
    {                                          // cat: 64 rows x 4 f4 (256 = 1/thread)
        int r = tid >> 2, cc = tid & 3;
        const float4* inp4 = (const float4*)(inputs + (size_t)row0 * NFEAT);
        float4 d = inp4[r * 16 + 12 + cc];
        __syncthreads();                       // scb ready (also covers numeric phase)
        s[r][48 + cc * 4 + 0] = scb[(cc * 4 + 0) * NCLS + (int)d.x];
        s[r][48 + cc * 4 + 1] = scb[(cc * 4 + 1) * NCLS + (int)d.y];
        s[r][48 + cc * 4 + 2] = scb[(cc * 4 + 2) * NCLS + (int)d.z];
        s[r][48 + cc * 4 + 3] = scb[(cc * 4 + 3) * NCLS + (int)d.w];
    }
    __syncthreads();

    float4* out4 = (float4*)(out + (size_t)row0 * NFEAT);
    #pragma unroll
    for (int i = 0; i < 4; i++) {             // 64 rows x 16 f4
        int v  = i * 256 + tid;
        int r  = v >> 4, c4 = v & 15;
        out4[v] = make_float4(s[r][4 * c4 + 0], s[r][4 * c4 + 1],
                              s[r][4 * c4 + 2], s[r][4 * c4 + 3]);
    }
}

extern "C" void kernel_launch(void* const* d_in, const int* in_sizes, int n_in,
                              void* d_out, int out_size)
{
    const float* inputs     = (const float*)d_in[0];
    const float* W0         = (const float*)d_in[1];
    const float* b0         = (const float*)d_in[2];
    const float* W1         = (const float*)d_in[3];
    const float* b1         = (const float*)d_in[4];
    const float* W2         = (const float*)d_in[5];
    const float* b2         = (const float*)d_in[6];
    const float* class_bias = (const float*)d_in[7];
    float* out = (float*)d_out;

    gam_setup_kernel<<<NNUM, 1024>>>(W0, b0, W1, b1, W2, b2);
    gam_pre_kernel<<<B_TOTAL / PRER, 256>>>(inputs);
    dim3 g2(B_TOTAL / LROWS, NNUM);           // 32 x 48
    gam_lut_kernel<<<g2, 256>>>();
    gam_post_kernel<<<B_TOTAL / PRER, 256>>>(inputs, class_bias, out);
}

// round 8
// speedup vs baseline: 6.9096x; 1.0056x over previous
#include <cuda_runtime.h>

#define B_TOTAL 131072
#define NFEAT   64
#define NNUM    48
#define NCAT    16
#define NCLS    32
#define H0      40
#define H1      20
#define TBL     1024
#define NCELL   4096
#define KCLAMP  1.0e4f
#define XSYNTH  -16.0f

// device-global scratch (allocation-free)
__device__ float          g_x[NNUM][TBL];     // knot x, padded +huge
__device__ float2         g_ys[NNUM][TBL];    // (y, slope-to-next)
__device__ unsigned short g_bk[NNUM][NCELL];  // bucket -> knot index
__device__ float          g_xT[NNUM * B_TOTAL];  // col-major x, overwritten with y in-place

// ---------------------------------------------------------------------------
// Setup: exact PWL table per numeric feature.
// Net is exactly PWL in scalar x: knots = layer0 zeros U h1 zero-crossings.
// ---------------------------------------------------------------------------
__global__ __launch_bounds__(1024)
void gam_setup_kernel(const float* __restrict__ W0, const float* __restrict__ b0,
                      const float* __restrict__ W1, const float* __restrict__ b1,
                      const float* __restrict__ W2, const float* __restrict__ b2)
{
    const int f   = blockIdx.x;
    const int tid = threadIdx.x;

    __shared__ float sa[H0], sc[H0], sk[H0];
    __shared__ float sH[H0 + 2][H1];
    __shared__ float list[TBL];
    __shared__ float sx[TBL];
    __shared__ float sW1[H0 * H1], sb1[H1], sW2[H1];
    __shared__ float syr, sb2v;
    __shared__ int   cnt;

    if (tid == 0) cnt = 0;
    if (tid < H0) { sa[tid] = W0[f * H0 + tid]; sc[tid] = b0[f * H0 + tid]; }
    for (int i = tid; i < H0 * H1; i += 1024) sW1[i] = W1[f * H0 * H1 + i];
    if (tid < H1) { sb1[tid] = b1[f * H1 + tid]; sW2[tid] = W2[f * H1 + tid]; }
    if (tid == 0) sb2v = b2[f];
    __syncthreads();

    // layer0 knots (clamped), stable rank-sort into sk
    if (tid < H0) {
        float a = sa[tid], c = sc[tid];
        float kx = (a != 0.0f) ? fminf(fmaxf(-c / a, -KCLAMP), KCLAMP) : KCLAMP;
        int r = 0;
        for (int j = 0; j < H0; j++) {
            float aj = sa[j], cj = sc[j];
            float kj = (aj != 0.0f) ? fminf(fmaxf(-cj / aj, -KCLAMP), KCLAMP) : KCLAMP;
            if (kj < kx || (kj == kx && j < tid)) r++;
        }
        sk[r] = kx;
    }
    __syncthreads();

    // h1[p] exactly at each sorted base knot + probes at sk0-1, sk39+1
    for (int idx = tid; idx < (H0 + 2) * H1; idx += 1024) {
        int k = idx / H1, p = idx % H1;
        float x = (k < H0) ? sk[k] : (k == H0 ? sk[0] - 1.0f : sk[H0 - 1] + 1.0f);
        float acc = sb1[p];
        for (int o = 0; o < H0; o++)
            acc += sW1[o * H1 + p] * fmaxf(sa[o] * x + sc[o], 0.0f);
        sH[k][p] = acc;
    }
    if (tid < H0) list[atomicAdd(&cnt, 1)] = sk[tid];
    if (tid == 0) list[atomicAdd(&cnt, 1)] = XSYNTH;   // synthetic left anchor
    __syncthreads();

    // interior zero-crossings of h1[p]
    for (int idx = tid; idx < (H0 - 1) * H1; idx += 1024) {
        int k = idx / H1, p = idx % H1;
        float y0 = sH[k][p], y1 = sH[k + 1][p];
        if ((y0 > 0.0f) != (y1 > 0.0f)) {
            float xs = sk[k] - y0 * (sk[k + 1] - sk[k]) / (y1 - y0);
            xs = fminf(fmaxf(xs, -KCLAMP), KCLAMP);
            list[atomicAdd(&cnt, 1)] = xs;
        }
    }
    // tail crossings (finite-difference slopes from probes)
    if (tid < H1) {
        int p = tid;
        float y0 = sH[0][p];
        float sl = sH[0][p] - sH[H0][p];
        if (sl != 0.0f && y0 != 0.0f && (y0 / sl) > 0.0f) {
            float xs = fminf(fmaxf(sk[0] - y0 / sl, -KCLAMP), KCLAMP);
            list[atomicAdd(&cnt, 1)] = xs;
        }
        float y1 = sH[H0 - 1][p];
        float sr = sH[H0 + 1][p] - sH[H0 - 1][p];
        if (sr != 0.0f && y1 != 0.0f && (y1 / sr) < 0.0f) {
            float xs = fminf(fmaxf(sk[H0 - 1] - y1 / sr, -KCLAMP), KCLAMP);
            list[atomicAdd(&cnt, 1)] = xs;
        }
    }
    __syncthreads();
    const int n = cnt;   // <= 862

    // stable rank-sort list[0..n) -> sx, pad with +huge
    for (int i = tid; i < n; i += 1024) {
        float v = list[i];
        int r = 0;
        for (int j = 0; j < n; j++) {
            float u = list[j];
            r += (u < v) || (u == v && j < i);
        }
        sx[r] = v;
    }
    for (int i = tid; i < TBL; i += 1024)
        if (i >= n) sx[i] = 3.4e38f;
    __syncthreads();

    // exact full-network evals at every knot + right probe
    for (int idx = tid; idx < n + 1; idx += 1024) {
        float x = (idx == n) ? sx[n - 1] + 1.0f : sx[idx];
        float h1v[H1];
        #pragma unroll
        for (int p = 0; p < H1; p++) h1v[p] = sb1[p];
        for (int o = 0; o < H0; o++) {
            float h0 = fmaxf(sa[o] * x + sc[o], 0.0f);
            #pragma unroll
            for (int p = 0; p < H1; p++) h1v[p] += sW1[o * H1 + p] * h0;
        }
        float yv = sb2v;
        #pragma unroll
        for (int p = 0; p < H1; p++) yv += sW2[p] * fmaxf(h1v[p], 0.0f);
        if (idx == n) syr = yv; else list[idx] = yv;
    }
    __syncthreads();

    // emit table (x, y, slope)
    for (int k = tid; k < TBL; k += 1024) {
        float xk = sx[k];
        float yk = (k < n) ? list[k] : 0.0f;
        float s = 0.0f;
        if (k < n - 1) {
            float dx = sx[k + 1] - xk;
            if (dx > 0.0f) s = (list[k + 1] - yk) / dx;
        } else if (k == n - 1) {
            s = syr - yk;                  // right tail (dx = 1)
        }
        g_x[f][k]  = xk;
        g_ys[f][k] = make_float2(yk, s);
    }
    // bucket LUT: cell c over [-8,8] -> last knot with x <= cell_left
    for (int c = tid; c < NCELL; c += 1024) {
        float cl = -8.0f + (float)c * (16.0f / NCELL);
        int k = 0;
        #pragma unroll
        for (int b = 512; b >= 1; b >>= 1) {
            int t = k + b;
            if (t < TBL && sx[t] <= cl) k = t;
        }
        g_bk[f][c] = (unsigned short)k;
    }
}

// ---------------------------------------------------------------------------
// K1 pre: 64 rows/block, numeric columns -> smem transpose -> g_xT
// ---------------------------------------------------------------------------
#define PRER 64

__global__ __launch_bounds__(256)
void gam_pre_kernel(const float* __restrict__ inputs)
{
    __shared__ float s[PRER][NNUM + 1];       // 64 x 49
    const int tid  = threadIdx.x;
    const int row0 = blockIdx.x * PRER;

    const float4* inp4 = (const float4*)(inputs + (size_t)row0 * NFEAT);
    #pragma unroll
    for (int i = 0; i < 3; i++) {             // 64 rows x 12 numeric f4
        int v  = i * 256 + tid;
        int r  = v / 12, c4 = v - r * 12;
        float4 d = __ldcs(&inp4[r * 16 + c4]);   // numeric sectors: last use
        s[r][c4 * 4 + 0] = d.x; s[r][c4 * 4 + 1] = d.y;
        s[r][c4 * 4 + 2] = d.z; s[r][c4 * 4 + 3] = d.w;
    }
    __syncthreads();

    #pragma unroll
    for (int i = 0; i < 3; i++) {             // 48 feats x 16 row-quads
        int v  = i * 256 + tid;
        int f  = v >> 4, rq = v & 15;
        float4 d = make_float4(s[4 * rq + 0][f], s[4 * rq + 1][f],
                               s[4 * rq + 2][f], s[4 * rq + 3][f]);
        ((float4*)(g_xT + (size_t)f * B_TOTAL + row0))[rq] = d;
    }
}

// ---------------------------------------------------------------------------
// K2 lut: in-place on g_xT (reads x, writes y to the same slots)
// ---------------------------------------------------------------------------
__device__ __forceinline__ float lut_eval(float xv, const float* tx,
                                          const float2* tys,
                                          const unsigned short* sb)
{
    int cell = __float2int_rz(fmaf(xv, (float)NCELL / 16.0f, (float)NCELL / 2));
    cell = max(0, min(NCELL - 1, cell));
    int k = sb[cell];
    while (tx[k + 1] <= xv) k++;
    while (k > 0 && tx[k] > xv) k--;          // guard: x below bucket grid
    float2 ys = tys[k];
    return fmaf(xv - tx[k], ys.y, ys.x);
}

#define LROWS 2048
__global__ __launch_bounds__(256)
void gam_lut_kernel()
{
    __shared__ float          tx[TBL];
    __shared__ float2         tys[TBL];
    __shared__ unsigned short sb[NCELL];
    const int f   = blockIdx.y;
    const int tid = threadIdx.x;

    ((float4*)tx)[tid]        = ((const float4*)g_x[f])[tid];
    ((float4*)tys)[tid]       = ((const float4*)g_ys[f])[tid];
    ((float4*)tys)[256 + tid] = ((const float4*)g_ys[f])[256 + tid];
    ((uint4*)sb)[tid]         = ((const uint4*)g_bk[f])[tid];
    ((uint4*)sb)[256 + tid]   = ((const uint4*)g_bk[f])[256 + tid];
    __syncthreads();

    float4* xc = (float4*)(g_xT + (size_t)f * B_TOTAL) + blockIdx.x * (LROWS / 4);
    #pragma unroll
    for (int g = 0; g < LROWS / 1024; g++) {
        float4 x4 = xc[g * 256 + tid];
        float4 y4;
        y4.x = lut_eval(x4.x, tx, tys, sb);
        y4.y = lut_eval(x4.y, tx, tys, sb);
        y4.z = lut_eval(x4.z, tx, tys, sb);
        y4.w = lut_eval(x4.w, tx, tys, sb);
        xc[g * 256 + tid] = y4;               // in-place overwrite
    }
}

// ---------------------------------------------------------------------------
// K3 post: g_xT (now y) numeric columns + inputs cat columns -> row-major out
// ---------------------------------------------------------------------------
__global__ __launch_bounds__(256)
void gam_post_kernel(const float* __restrict__ inputs,
                     const float* __restrict__ class_bias,
                     float* __restrict__ out)
{
    __shared__ float s[PRER][NFEAT + 1];      // 64 x 65
    __shared__ float scb[NCAT * NCLS];
    const int tid  = threadIdx.x;
    const int row0 = blockIdx.x * PRER;

    if (tid < 128) ((float4*)scb)[tid] = ((const float4*)class_bias)[tid];

    #pragma unroll
    for (int i = 0; i < 3; i++) {             // numeric: 48 feats x 16 quads
        int v  = i * 256 + tid;
        int f  = v >> 4, rq = v & 15;
        float4 d = __ldlu(&((const float4*)(g_xT + (size_t)f * B_TOTAL + row0))[rq]);
        s[4 * rq + 0][f] = d.x; s[4 * rq + 1][f] = d.y;
        s[4 * rq + 2][f] = d.z; s[4 * rq + 3][f] = d.w;
    }
    {                                          // cat: 64 rows x 4 f4 (256 = 1/thread)
        int r = tid >> 2, cc = tid & 3;
        const float4* inp4 = (const float4*)(inputs + (size_t)row0 * NFEAT);
        float4 d = __ldcs(&inp4[r * 16 + 12 + cc]);   // cat sectors: last use
        __syncthreads();                       // scb ready (also covers numeric phase)
        s[r][48 + cc * 4 + 0] = scb[(cc * 4 + 0) * NCLS + (int)d.x];
        s[r][48 + cc * 4 + 1] = scb[(cc * 4 + 1) * NCLS + (int)d.y];
        s[r][48 + cc * 4 + 2] = scb[(cc * 4 + 2) * NCLS + (int)d.z];
        s[r][48 + cc * 4 + 3] = scb[(cc * 4 + 3) * NCLS + (int)d.w];
    }
    __syncthreads();

    float4* out4 = (float4*)(out + (size_t)row0 * NFEAT);
    #pragma unroll
    for (int i = 0; i < 4; i++) {             // 64 rows x 16 f4 — streaming stores
        int v  = i * 256 + tid;
        int r  = v >> 4, c4 = v & 15;
        __stcs(&out4[v], make_float4(s[r][4 * c4 + 0], s[r][4 * c4 + 1],
                                     s[r][4 * c4 + 2], s[r][4 * c4 + 3]));
    }
}

extern "C" void kernel_launch(void* const* d_in, const int* in_sizes, int n_in,
                              void* d_out, int out_size)
{
    const float* inputs     = (const float*)d_in[0];
    const float* W0         = (const float*)d_in[1];
    const float* b0         = (const float*)d_in[2];
    const float* W1         = (const float*)d_in[3];
    const float* b1         = (const float*)d_in[4];
    const float* W2         = (const float*)d_in[5];
    const float* b2         = (const float*)d_in[6];
    const float* class_bias = (const float*)d_in[7];
    float* out = (float*)d_out;

    gam_setup_kernel<<<NNUM, 1024>>>(W0, b0, W1, b1, W2, b2);
    gam_pre_kernel<<<B_TOTAL / PRER, 256>>>(inputs);
    dim3 g2(B_TOTAL / LROWS, NNUM);           // 64 x 48
    gam_lut_kernel<<<g2, 256>>>();
    gam_post_kernel<<<B_TOTAL / PRER, 256>>>(inputs, class_bias, out);
}